// round 7
// baseline (speedup 1.0000x reference)
#include <cuda_runtime.h>
#include <math.h>

#define N_ROWS 500000
#define TILE_M 64
#define N_TILES ((N_ROWS + TILE_M - 1) / TILE_M)   // 7813
#define TPB 256
#define NWARP (TPB / 32)
#define PGRID 304

typedef unsigned int u32;

#define OUT_SCALAR ((size_t)N_ROWS * 100)

// ---------------- global accumulators + z2 scratch ----------------
__device__ double g_p0;
__device__ double g_sq;
__device__ double g_diff;
__device__ double g_mu[100];
__device__ u32 g_z2[(size_t)N_TILES * TILE_M * 56];   // tf32 bits, [row][56]

__global__ void init_kernel() {
    int t = threadIdx.x;
    if (t == 0) { g_p0 = 0.0; g_sq = 0.0; g_diff = 0.0; }
    if (t < 100) g_mu[t] = 0.0;
}

// ---------------- tf32 / mma helpers ----------------
__device__ __forceinline__ u32 tf32c(float f) {
    u32 r; asm("cvt.rna.tf32.f32 %0, %1;" : "=r"(r) : "f"(f)); return r;
}
__device__ __forceinline__ void mma8(float* d, u32 a0, u32 a1, u32 a2, u32 a3,
                                     u32 b0, u32 b1) {
    asm("mma.sync.aligned.m16n8k8.row.col.f32.tf32.tf32.f32 "
        "{%0,%1,%2,%3}, {%4,%5,%6,%7}, {%8,%9}, {%0,%1,%2,%3};"
        : "+f"(d[0]), "+f"(d[1]), "+f"(d[2]), "+f"(d[3])
        : "r"(a0), "r"(a1), "r"(a2), "r"(a3), "r"(b0), "r"(b1));
}

// One k-segment of a 2mt x 2nt warp block. A[row][k], W[n][k] (both smem tf32).
__device__ __forceinline__ void mma_seg(
    float c[2][2][4],
    const u32* __restrict__ W, int ws,
    const u32* __restrict__ A, int as,
    int nsteps, int k0w,
    int mt0, int nt0, int nts, int qr, int qc)
{
    const u32* ap0 = A + (mt0 * 16 + qr) * as + qc;
    const u32* ap1 = ap0 + 16 * as;
    const u32* bp0 = W + (nt0 * 8 + qr) * ws + k0w + qc;
    const u32* bp1 = bp0 + 8 * ws;
    const int as8 = 8 * as;
    #pragma unroll 1
    for (int s = 0; s < nsteps; s++) {
        u32 a00 = ap0[0], a01 = ap0[as8], a02 = ap0[4], a03 = ap0[as8 + 4];
        u32 a10 = ap1[0], a11 = ap1[as8], a12 = ap1[4], a13 = ap1[as8 + 4];
        u32 b00 = bp0[0], b01 = bp0[4];
        mma8(c[0][0], a00, a01, a02, a03, b00, b01);
        mma8(c[1][0], a10, a11, a12, a13, b00, b01);
        if (nts > 1) {
            u32 b10 = bp1[0], b11 = bp1[4];
            mma8(c[0][1], a00, a01, a02, a03, b10, b11);
            mma8(c[1][1], a10, a11, a12, a13, b10, b11);
        }
        ap0 += 8; ap1 += 8; bp0 += 8; bp1 += 8;
    }
}

// Full block: two segments (concat routing) + relu/bias/tf32 epilogue to smem.
__device__ __forceinline__ void gemm_block(
    const u32* __restrict__ W, int ws, const float* __restrict__ bias,
    const u32* __restrict__ A0, int as0, int split,
    const u32* __restrict__ A1, int as1, int KS,
    int mt0, int nt0, int nts,
    u32* __restrict__ outb, int os, int lane)
{
    const int qr = lane >> 2, qc = lane & 3;
    float c[2][2][4] = {};
    mma_seg(c, W, ws, A0, as0, split, 0, mt0, nt0, nts, qr, qc);
    if (KS > split)
        mma_seg(c, W, ws, A1, as1, KS - split, split * 8, mt0, nt0, nts, qr, qc);

    #pragma unroll
    for (int mi = 0; mi < 2; mi++)
    #pragma unroll
    for (int ni = 0; ni < 2; ni++) {
        if (ni >= nts) continue;
        int col = (nt0 + ni) * 8 + 2 * qc;
        float b0v = bias[col], b1v = bias[col + 1];
        int r = mt0 * 16 + mi * 16 + qr;
        float v0 = fmaxf(c[mi][ni][0] + b0v, 0.0f);
        float v1 = fmaxf(c[mi][ni][1] + b1v, 0.0f);
        float v2 = fmaxf(c[mi][ni][2] + b0v, 0.0f);
        float v3 = fmaxf(c[mi][ni][3] + b1v, 0.0f);
        *(uint2*)(outb + r * os + col) = make_uint2(tf32c(v0), tf32c(v1));
        *(uint2*)(outb + (r + 8) * os + col) = make_uint2(tf32c(v2), tf32c(v3));
    }
}

__device__ __forceinline__ void run_layer(
    u32* sm, float* smf, int warp, int lane,
    int wofs, int ws, int bofs,
    int a0ofs, int as0, int split, int a1ofs, int as1,
    int KS, int NT, int oofs, int os)
{
    int nblocks = 2 * ((NT + 1) >> 1);
    for (int b = warp; b < nblocks; b += NWARP) {
        int mt0 = (b & 1) * 2, nt0 = (b >> 1) * 2;
        int nts = (NT - nt0 >= 2) ? 2 : 1;
        gemm_block(sm + wofs, ws, smf + bofs, sm + a0ofs, as0, split,
                   sm + a1ofs, as1, KS, mt0, nt0, nts, sm + oofs, os, lane);
    }
}

// ================= K1: layers 1,2  (persistent) =================
// smem words:
#define W1_OFS   0        // 104 x 212
#define W12_OFS  22048    // 56 x 108
#define B1_OFS   28096    // 104
#define B12_OFS  28200    // 56
#define XS_OFS   28256    // 64 x 108
#define HS_OFS   35168    // 64 x 108
#define Z1_OFS   42080    // 64 x 108
#define Z2_OFS   48992    // 64 x 60
#define K1_WORDS 52832
#define K1_SMEM  (K1_WORDS * 4)

__global__ void __launch_bounds__(TPB, 1) k1(
    const float* __restrict__ x, const float* __restrict__ h,
    const float* __restrict__ w1, const float* __restrict__ b1,
    const float* __restrict__ w12, const float* __restrict__ b12)
{
    extern __shared__ u32 sm[];
    float* smf = (float*)sm;
    const int tid = threadIdx.x, lane = tid & 31, warp = tid >> 5;

    // stage weights (zero pads first)
    for (int i = tid; i < XS_OFS; i += TPB) sm[i] = 0u;
    __syncthreads();
    for (int i = tid; i < 20000; i += TPB) {
        int n = i / 200, k = i % 200;
        int kk = (k < 100) ? k : k + 4;            // [x 104 | h 104] k-space
        sm[W1_OFS + n * 212 + kk] = tf32c(w1[i]);
    }
    for (int i = tid; i < 5000; i += TPB) {
        int n = i / 100, k = i % 100;
        sm[W12_OFS + n * 108 + k] = tf32c(w12[i]);
    }
    for (int i = tid; i < 100; i += TPB) smf[B1_OFS + i] = b1[i];
    for (int i = tid; i < 50;  i += TPB) smf[B12_OFS + i] = b12[i];
    __syncthreads();

    for (int tile = blockIdx.x; tile < N_TILES; tile += gridDim.x) {
        const size_t r0 = (size_t)tile * TILE_M;
        // load x,h tiles (tf32), zero pads + tail rows
        for (int i = tid; i < TILE_M * 108; i += TPB) {
            int r = i / 108, c = i % 108;
            float xv = 0.0f, hv = 0.0f;
            if (c < 100 && r0 + r < N_ROWS) {
                xv = x[(r0 + r) * 100 + c];
                hv = h[(r0 + r) * 100 + c];
            }
            sm[XS_OFS + i] = tf32c(xv);
            sm[HS_OFS + i] = tf32c(hv);
        }
        __syncthreads();
        // L1: [x|h] -> z1 (100, pad 104). K=208, split 13.
        run_layer(sm, smf, warp, lane, W1_OFS, 212, B1_OFS,
                  XS_OFS, 108, 13, HS_OFS, 108, 26, 13, Z1_OFS, 108);
        __syncthreads();
        // L2: z1 -> z2 (50, pad 56). K=104.
        run_layer(sm, smf, warp, lane, W12_OFS, 108, B12_OFS,
                  Z1_OFS, 108, 13, Z1_OFS, 108, 13, 7, Z2_OFS, 60);
        __syncthreads();
        // copy z2 -> gmem scratch (coalesced)
        u32* zg = g_z2 + (size_t)tile * TILE_M * 56;
        for (int i = tid; i < TILE_M * 56; i += TPB) {
            int r = i / 56, c = i % 56;
            zg[i] = sm[Z2_OFS + r * 60 + c];
        }
        __syncthreads();
    }
}

// ================= K2: layers 3..6 + part0  (persistent) =================
#define W13_OFS  0        // 32 x 164
#define W14_OFS  5248     // 24 x 36
#define W15_OFS  6112     // 40 x 132
#define W2_OFS   11392    // 104 x 44
#define B13_OFS  15968
#define B14_OFS  16000
#define B15_OFS  16024
#define B2_OFS   16064
#define HS2_OFS  16168    // 64 x 108
#define Z2B_OFS  23080    // 64 x 60
#define Z3_OFS   26920    // 64 x 36
#define Z4_OFS   29224    // 64 x 28
#define Z5_OFS   31016    // 64 x 44
#define K2_WORDS 33832
#define K2_SMEM  (K2_WORDS * 4)

__global__ void __launch_bounds__(TPB, 1) k2(
    const float* __restrict__ x, const float* __restrict__ h,
    const float* __restrict__ w13, const float* __restrict__ b13,
    const float* __restrict__ w14, const float* __restrict__ b14,
    const float* __restrict__ w15, const float* __restrict__ b15,
    const float* __restrict__ w2,  const float* __restrict__ b2,
    float* __restrict__ out)
{
    extern __shared__ u32 sm[];
    float* smf = (float*)sm;
    const int tid = threadIdx.x, lane = tid & 31, warp = tid >> 5;
    const int qr = lane >> 2, qc = lane & 3;

    for (int i = tid; i < HS2_OFS; i += TPB) sm[i] = 0u;
    __syncthreads();
    for (int i = tid; i < 4500; i += TPB) {        // w13 [30][150]: k<50 z2 | h
        int n = i / 150, k = i % 150;
        int kk = (k < 50) ? k : k + 6;             // [z2 56 | h 104]
        sm[W13_OFS + n * 164 + kk] = tf32c(w13[i]);
    }
    for (int i = tid; i < 600; i += TPB) {         // w14 [20][30]
        int n = i / 30, k = i % 30;
        sm[W14_OFS + n * 36 + k] = tf32c(w14[i]);
    }
    for (int i = tid; i < 4800; i += TPB) {        // w15 [40][120]: k<20 z4 | h
        int n = i / 120, k = i % 120;
        int kk = (k < 20) ? k : k + 4;             // [z4 24 | h 104]
        sm[W15_OFS + n * 132 + kk] = tf32c(w15[i]);
    }
    for (int i = tid; i < 4000; i += TPB) {        // w2 [100][40]
        int n = i / 40, k = i % 40;
        sm[W2_OFS + n * 44 + k] = tf32c(w2[i]);
    }
    for (int i = tid; i < 30;  i += TPB) smf[B13_OFS + i] = b13[i];
    for (int i = tid; i < 20;  i += TPB) smf[B14_OFS + i] = b14[i];
    for (int i = tid; i < 40;  i += TPB) smf[B15_OFS + i] = b15[i];
    for (int i = tid; i < 100; i += TPB) smf[B2_OFS + i] = b2[i];
    __syncthreads();

    float p0 = 0.0f;

    for (int tile = blockIdx.x; tile < N_TILES; tile += gridDim.x) {
        const size_t r0 = (size_t)tile * TILE_M;
        for (int i = tid; i < TILE_M * 108; i += TPB) {
            int r = i / 108, c = i % 108;
            float hv = 0.0f;
            if (c < 100 && r0 + r < N_ROWS) hv = h[(r0 + r) * 100 + c];
            sm[HS2_OFS + i] = tf32c(hv);
        }
        const u32* zg = g_z2 + (size_t)tile * TILE_M * 56;
        for (int i = tid; i < TILE_M * 60; i += TPB) {
            int r = i / 60, c = i % 60;
            sm[Z2B_OFS + i] = (c < 56) ? zg[r * 56 + c] : 0u;
        }
        __syncthreads();
        // L3: [z2|h] -> z3 (30 pad 32). K=160, split 7.
        run_layer(sm, smf, warp, lane, W13_OFS, 164, B13_OFS,
                  Z2B_OFS, 60, 7, HS2_OFS, 108, 20, 4, Z3_OFS, 36);
        __syncthreads();
        // L4: z3 -> z4 (20 pad 24). K=32.
        run_layer(sm, smf, warp, lane, W14_OFS, 36, B14_OFS,
                  Z3_OFS, 36, 4, Z3_OFS, 36, 4, 3, Z4_OFS, 28);
        __syncthreads();
        // L5: [z4|h] -> z5 (40). K=128, split 3.
        run_layer(sm, smf, warp, lane, W15_OFS, 132, B15_OFS,
                  Z4_OFS, 28, 3, HS2_OFS, 108, 16, 5, Z5_OFS, 44);
        __syncthreads();
        // L6: z5 -> f (fp32 out, no relu) + fused part0
        for (int b = warp; b < 14; b += NWARP) {
            int mt0 = (b & 1) * 2, nt0 = (b >> 1) * 2;
            int nts = (13 - nt0 >= 2) ? 2 : 1;
            float c[2][2][4] = {};
            mma_seg(c, sm + W2_OFS, 44, sm + Z5_OFS, 44, 5, 0,
                    mt0, nt0, nts, qr, qc);
            #pragma unroll
            for (int mi = 0; mi < 2; mi++)
            #pragma unroll
            for (int ni = 0; ni < 2; ni++) {
                if (ni >= nts) continue;
                int col = (nt0 + ni) * 8 + 2 * qc;
                if (col >= 100) continue;
                float b0v = smf[B2_OFS + col], b1v = smf[B2_OFS + col + 1];
                #pragma unroll
                for (int hh = 0; hh < 2; hh++) {
                    size_t grow = r0 + mt0 * 16 + mi * 16 + qr + hh * 8;
                    float v0 = c[mi][ni][2 * hh]     + b0v;
                    float v1 = c[mi][ni][2 * hh + 1] + b1v;
                    if (grow < N_ROWS) {
                        *(float2*)(out + grow * 100 + col) = make_float2(v0, v1);
                        if (grow + 1 < N_ROWS) {
                            float2 xn = *(const float2*)(x + (grow + 1) * 100 + col);
                            float d0 = v0 - xn.x, d1 = v1 - xn.y;
                            p0 += d0 * d0 + d1 * d1;
                        }
                    }
                }
            }
        }
        __syncthreads();
    }

    // block reduction of part0
    #pragma unroll
    for (int o = 16; o > 0; o >>= 1) p0 += __shfl_down_sync(0xffffffffu, p0, o);
    __shared__ float red[NWARP];
    if (lane == 0) red[warp] = p0;
    __syncthreads();
    if (tid == 0) {
        float acc = 0.0f;
        #pragma unroll
        for (int i = 0; i < NWARP; i++) acc += red[i];
        atomicAdd(&g_p0, (double)acc);
    }
}

// ---------------- h statistics (float inner accumulation) ----------------
#define HS_ROWS 512
__global__ void h_stats(const float* __restrict__ h) {
    const int col = threadIdx.x;
    const long long r0 = (long long)blockIdx.x * HS_ROWS;
    long long r1 = r0 + HS_ROWS; if (r1 > N_ROWS) r1 = N_ROWS;

    float csum = 0.0f, sq = 0.0f, dif = 0.0f;
    if (col < 100 && r0 < N_ROWS) {
        float prev = h[r0 * 100 + col];
        csum = prev; sq = prev * prev;
        #pragma unroll 8
        for (long long r = r0 + 1; r < r1; ++r) {
            float v = h[r * 100 + col];
            csum += v;
            sq   = fmaf(v, v, sq);
            dif  += fabsf(v - prev);
            prev = v;
        }
        if (r1 < N_ROWS) {
            float v = h[r1 * 100 + col];
            dif += fabsf(v - prev);
        }
        atomicAdd(&g_mu[col], (double)csum);
    }

    __shared__ float ssq[128], sdf[128];
    ssq[threadIdx.x] = sq; sdf[threadIdx.x] = dif;
    __syncthreads();
    for (int off = 64; off > 0; off >>= 1) {
        if (threadIdx.x < off) {
            ssq[threadIdx.x] += ssq[threadIdx.x + off];
            sdf[threadIdx.x] += sdf[threadIdx.x + off];
        }
        __syncthreads();
    }
    if (threadIdx.x == 0) {
        atomicAdd(&g_sq,   (double)ssq[0]);
        atomicAdd(&g_diff, (double)sdf[0]);
    }
}

// ---------------- finalize scalars ----------------
__global__ void finalize(float* __restrict__ out) {
    __shared__ double smd[128];
    const int t = threadIdx.x;
    smd[t] = (t < 100) ? fabs(g_mu[t] / (double)N_ROWS) : 0.0;
    __syncthreads();
    for (int off = 64; off > 0; off >>= 1) {
        if (t < off) smd[t] += smd[t + off];
        __syncthreads();
    }
    if (t == 0) {
        out[OUT_SCALAR + 0] = (float)(sqrt(g_p0) / (double)(N_ROWS - 1));
        out[OUT_SCALAR + 1] = (float)(smd[0] / 100.0);
        out[OUT_SCALAR + 2] = (float)fabs(g_sq / (double)N_ROWS / 100.0 - 1.0);
        out[OUT_SCALAR + 3] = (float)(g_diff / (double)(N_ROWS - 1) / 100.0);
    }
}

// ---------------- launch ----------------
extern "C" void kernel_launch(void* const* d_in, const int* in_sizes, int n_in,
                              void* d_out, int out_size) {
    const float* x   = (const float*)d_in[0];
    const float* h   = (const float*)d_in[1];
    const float* w1  = (const float*)d_in[2];
    const float* b1  = (const float*)d_in[3];
    const float* w12 = (const float*)d_in[4];
    const float* b12 = (const float*)d_in[5];
    const float* w13 = (const float*)d_in[6];
    const float* b13 = (const float*)d_in[7];
    const float* w14 = (const float*)d_in[8];
    const float* b14 = (const float*)d_in[9];
    const float* w15 = (const float*)d_in[10];
    const float* b15 = (const float*)d_in[11];
    const float* w2  = (const float*)d_in[12];
    const float* b2  = (const float*)d_in[13];
    float* out = (float*)d_out;

    (void)in_sizes; (void)n_in; (void)out_size;

    cudaFuncSetAttribute(k1, cudaFuncAttributeMaxDynamicSharedMemorySize, K1_SMEM);
    cudaFuncSetAttribute(k2, cudaFuncAttributeMaxDynamicSharedMemorySize, K2_SMEM);

    init_kernel<<<1, 128>>>();
    k1<<<PGRID, TPB, K1_SMEM>>>(x, h, w1, b1, w12, b12);
    k2<<<PGRID, TPB, K2_SMEM>>>(x, h, w13, b13, w14, b14, w15, b15, w2, b2, out);
    h_stats<<<(N_ROWS + HS_ROWS - 1) / HS_ROWS, 128>>>(h);
    finalize<<<1, 128>>>(out);
}